// round 5
// baseline (speedup 1.0000x reference)
#include <cuda_runtime.h>
#include <math.h>

#define NN 100000
#define NE 1600000
#define DD 128
#define SCAN_BLK 1024
#define NSB ((NN + SCAN_BLK - 1) / SCAN_BLK)   // 98 scan blocks

// ---------------- scratch (device globals; no allocation) ----------------
__device__ alignas(16) float g_xs[(size_t)2 * NN * DD];     // layer0/1 outputs (102.4 MB)
__device__ alignas(16) int   g_deg[NN];
__device__ alignas(16) int   g_cur[NN];
__device__ alignas(16) int   g_srcs[NE];
__device__ alignas(16) int   g_off[NN + 1];
__device__ alignas(16) int   g_bsum[NSB];
__device__ alignas(16) int   g_bpre[NSB];
__device__ int g_is64;

// ---------------- packed f32x2 helpers (Blackwell FFMA2) ----------------
__device__ __forceinline__ unsigned long long pk2(float x, float y) {
    unsigned long long r;
    asm("mov.b64 %0, {%1, %2};" : "=l"(r) : "f"(x), "f"(y));
    return r;
}
__device__ __forceinline__ void fma2(unsigned long long& d, unsigned long long a, unsigned long long b) {
    asm("fma.rn.f32x2 %0, %1, %2, %0;" : "+l"(d) : "l"(a), "l"(b));
}
__device__ __forceinline__ void upk2(float& x, float& y, unsigned long long v) {
    asm("mov.b64 {%0, %1}, %2;" : "=f"(x), "=f"(y) : "l"(v));
}

// ---------------- dtype probe: int32 vs int64 edge_index ----------------
__global__ void k_detect(const int* __restrict__ ei32) {
    int lane = threadIdx.x;
    int nz = 0;
#pragma unroll
    for (int i = 0; i < 2; i++) {
        int w = ei32[2 * (lane + 32 * i) + 1];
        nz |= (w != 0);
    }
    unsigned any = __ballot_sync(0xffffffffu, nz);
    if (lane == 0) g_is64 = (any == 0u) ? 1 : 0;
}

// ---------------- CSR build ----------------
__global__ void k_zero() {
    int i = blockIdx.x * blockDim.x + threadIdx.x;
    if (i < NN) g_deg[i] = 0;
}

__global__ void k_hist(const int* __restrict__ ei32) {
    int e = blockIdx.x * blockDim.x + threadIdx.x;
    if (e < NE) {
        int is64 = g_is64;
        unsigned d = is64 ? (unsigned)ei32[2 * (NE + e)] : (unsigned)ei32[NE + e];
        if (d < NN) atomicAdd(&g_deg[d], 1);
    }
}

__global__ void k_scan1() {
    __shared__ int ws[32];
    int i = blockIdx.x * SCAN_BLK + threadIdx.x;
    int v = (i < NN) ? g_deg[i] : 0;
    int s = v;
#pragma unroll
    for (int o = 16; o; o >>= 1) s += __shfl_xor_sync(0xffffffffu, s, o);
    if ((threadIdx.x & 31) == 0) ws[threadIdx.x >> 5] = s;
    __syncthreads();
    if (threadIdx.x < 32) {
        int t = ws[threadIdx.x];
#pragma unroll
        for (int o = 16; o; o >>= 1) t += __shfl_xor_sync(0xffffffffu, t, o);
        if (threadIdx.x == 0) g_bsum[blockIdx.x] = t;
    }
}

__global__ void k_scan2() {
    __shared__ int warp_incl[4];
    int t = threadIdx.x;
    int v = (t < NSB) ? g_bsum[t] : 0;
    int incl = v;
#pragma unroll
    for (int o = 1; o < 32; o <<= 1) {
        int u = __shfl_up_sync(0xffffffffu, incl, o);
        if ((t & 31) >= o) incl += u;
    }
    if ((t & 31) == 31) warp_incl[t >> 5] = incl;
    __syncthreads();
    int base = 0;
#pragma unroll
    for (int w = 0; w < 4; w++)
        if ((t >> 5) > w) base += warp_incl[w];
    incl += base;
    if (t < NSB) g_bpre[t] = incl - v;
    if (t == NSB - 1) g_off[NN] = incl;
}

__global__ void k_scan3() {
    __shared__ int s[SCAN_BLK];
    int t = threadIdx.x;
    int i = blockIdx.x * SCAN_BLK + t;
    int v = (i < NN) ? g_deg[i] : 0;
    s[t] = v;
    __syncthreads();
    for (int o = 1; o < SCAN_BLK; o <<= 1) {
        int u = (t >= o) ? s[t - o] : 0;
        __syncthreads();
        s[t] += u;
        __syncthreads();
    }
    if (i < NN) {
        int off = g_bpre[blockIdx.x] + s[t] - v;
        g_off[i] = off;
        g_cur[i] = off;
    }
}

__global__ void k_scatter(const int* __restrict__ ei32) {
    int e = blockIdx.x * blockDim.x + threadIdx.x;
    if (e < NE) {
        int is64 = g_is64;
        unsigned d    = is64 ? (unsigned)ei32[2 * (NE + e)] : (unsigned)ei32[NE + e];
        unsigned srcv = is64 ? (unsigned)ei32[2 * e]        : (unsigned)ei32[e];
        if (d < NN && srcv < NN) {
            int pos = atomicAdd(&g_cur[d], 1);
            g_srcs[pos] = (int)srcv;
        }
    }
}

// ---------------- fused layer: gather + MLP (+ readout on last layer) ----------------
__device__ __forceinline__ int aswz(int k, int c) {
    return (c ^ (c >> 3) ^ ((k >> 2) & 7)) & 31;
}

__global__ __launch_bounds__(256, 1)
void k_layer(const float* __restrict__ x0,
             const float* __restrict__ W1, const float* __restrict__ b1,
             const float* __restrict__ W2, const float* __restrict__ b2,
             const float* __restrict__ Wm, const float* __restrict__ bm,
             float* __restrict__ final_out, int layer)
{
    extern __shared__ float sm[];
    float* As  = sm;                 // 128*128 floats (swizzled, k-major)
    float* Ws1 = sm + 128 * 128;
    float* Ws2 = Ws1 + 128 * 128;
    float4* As4 = (float4*)As;

    const int tid  = threadIdx.x;
    const int base = blockIdx.x * 128;
    const int wid  = tid >> 5;
    const int lane = tid & 31;
    const int m0 = (tid & 15) * 8;
    const int n0 = (tid >> 4) * 8;
    const int ca = m0 >> 2;

    // weights -> smem
    {
        const float4* W1_4 = (const float4*)W1;
        const float4* W2_4 = (const float4*)W2;
        float4* Ws1_4 = (float4*)Ws1;
        float4* Ws2_4 = (float4*)Ws2;
#pragma unroll
        for (int i = 0; i < 16; i++) {
            int idx = tid + i * 256;
            Ws1_4[idx] = W1_4[idx];
            Ws2_4[idx] = W2_4[idx];
        }
    }

    // fused gather: As[k-major, swizzled] = x[node] + sum_{in-edges} x[src]
    const float* xin = (layer == 0) ? x0 : (g_xs + (size_t)(layer - 1) * NN * DD);
    const float4* x4 = (const float4*)xin;
#pragma unroll 1
    for (int it = 0; it < 16; it++) {
        int m = wid + it * 8;            // 0..127
        int node = base + m;
        float4 v = make_float4(0.f, 0.f, 0.f, 0.f);
        if (node < NN) {
            v = x4[(size_t)node * 32 + lane];
            int j = g_off[node], end = g_off[node + 1];
            for (; j + 1 < end; j += 2) {
                int s0 = g_srcs[j], s1 = g_srcs[j + 1];
                float4 a = __ldg(&x4[(size_t)s0 * 32 + lane]);
                float4 b = __ldg(&x4[(size_t)s1 * 32 + lane]);
                v.x += a.x + b.x; v.y += a.y + b.y;
                v.z += a.z + b.z; v.w += a.w + b.w;
            }
            if (j < end) {
                int s0 = g_srcs[j];
                float4 a = __ldg(&x4[(size_t)s0 * 32 + lane]);
                v.x += a.x; v.y += a.y; v.z += a.z; v.w += a.w;
            }
        }
        int c = m >> 2, mb = m & 3;
        int k = lane * 4;
        As[(k + 0) * 128 + aswz(k + 0, c) * 4 + mb] = v.x;
        As[(k + 1) * 128 + aswz(k + 1, c) * 4 + mb] = v.y;
        As[(k + 2) * 128 + aswz(k + 2, c) * 4 + mb] = v.z;
        As[(k + 3) * 128 + aswz(k + 3, c) * 4 + mb] = v.w;
    }
    __syncthreads();

    unsigned long long accp[8][4];
#pragma unroll
    for (int i = 0; i < 8; i++)
#pragma unroll
        for (int j = 0; j < 4; j++) accp[i][j] = 0ull;

    // GEMM1: h = agg @ W1 (FFMA2)
#pragma unroll 2
    for (int k = 0; k < 128; k++) {
        float4 a0 = As4[k * 32 + aswz(k, ca)];
        float4 a1 = As4[k * 32 + aswz(k, ca + 1)];
        const float4* wrow = (const float4*)(Ws1 + k * 128 + n0);
        float4 w0 = wrow[0], w1 = wrow[1];
        unsigned long long wp[4] = {pk2(w0.x, w0.y), pk2(w0.z, w0.w),
                                    pk2(w1.x, w1.y), pk2(w1.z, w1.w)};
        float a[8] = {a0.x, a0.y, a0.z, a0.w, a1.x, a1.y, a1.z, a1.w};
#pragma unroll
        for (int i = 0; i < 8; i++) {
            unsigned long long ap = pk2(a[i], a[i]);
#pragma unroll
            for (int j = 0; j < 4; j++) fma2(accp[i][j], ap, wp[j]);
        }
    }

    float acc[8][8];
#pragma unroll
    for (int i = 0; i < 8; i++)
#pragma unroll
        for (int j = 0; j < 4; j++) upk2(acc[i][2 * j], acc[i][2 * j + 1], accp[i][j]);
#pragma unroll
    for (int j = 0; j < 8; j++) {
        float bj = __ldg(&b1[n0 + j]);
#pragma unroll
        for (int i = 0; i < 8; i++) acc[i][j] = fmaxf(acc[i][j] + bj, 0.f);
    }

    __syncthreads();
#pragma unroll
    for (int j = 0; j < 8; j++) {
        int k2 = n0 + j;
        As4[k2 * 32 + aswz(k2, ca)]     = make_float4(acc[0][j], acc[1][j], acc[2][j], acc[3][j]);
        As4[k2 * 32 + aswz(k2, ca + 1)] = make_float4(acc[4][j], acc[5][j], acc[6][j], acc[7][j]);
    }
    __syncthreads();

#pragma unroll
    for (int i = 0; i < 8; i++)
#pragma unroll
        for (int j = 0; j < 4; j++) accp[i][j] = 0ull;

    // GEMM2: out = h @ W2 (FFMA2)
#pragma unroll 2
    for (int k = 0; k < 128; k++) {
        float4 a0 = As4[k * 32 + aswz(k, ca)];
        float4 a1 = As4[k * 32 + aswz(k, ca + 1)];
        const float4* wrow = (const float4*)(Ws2 + k * 128 + n0);
        float4 w0 = wrow[0], w1 = wrow[1];
        unsigned long long wp[4] = {pk2(w0.x, w0.y), pk2(w0.z, w0.w),
                                    pk2(w1.x, w1.y), pk2(w1.z, w1.w)};
        float a[8] = {a0.x, a0.y, a0.z, a0.w, a1.x, a1.y, a1.z, a1.w};
#pragma unroll
        for (int i = 0; i < 8; i++) {
            unsigned long long ap = pk2(a[i], a[i]);
#pragma unroll
            for (int j = 0; j < 4; j++) fma2(accp[i][j], ap, wp[j]);
        }
    }

#pragma unroll
    for (int i = 0; i < 8; i++)
#pragma unroll
        for (int j = 0; j < 4; j++) upk2(acc[i][2 * j], acc[i][2 * j + 1], accp[i][j]);

    float bj2[8];
#pragma unroll
    for (int j = 0; j < 8; j++) bj2[j] = __ldg(&b2[n0 + j]);
#pragma unroll
    for (int i = 0; i < 8; i++)
#pragma unroll
        for (int j = 0; j < 8; j++) acc[i][j] += bj2[j];

    if (layer < 2) {
        // relu + store to g_xs[layer]
        float* out = g_xs + (size_t)layer * NN * DD;
        float4* out4 = (float4*)out;
#pragma unroll
        for (int i = 0; i < 8; i++) {
            int m = base + m0 + i;
            if (m < NN) {
                float4 o0, o1;
                o0.x = fmaxf(acc[i][0], 0.f); o0.y = fmaxf(acc[i][1], 0.f);
                o0.z = fmaxf(acc[i][2], 0.f); o0.w = fmaxf(acc[i][3], 0.f);
                o1.x = fmaxf(acc[i][4], 0.f); o1.y = fmaxf(acc[i][5], 0.f);
                o1.z = fmaxf(acc[i][6], 0.f); o1.w = fmaxf(acc[i][7], 0.f);
                out4[(size_t)m * 32 + (n0 >> 2)]     = o0;
                out4[(size_t)m * 32 + (n0 >> 2) + 1] = o1;
            }
        }
    } else {
        // fused readout: z[m] = x1·Wm[0:128] + x2·Wm[128:256] + x3·Wm[256:384] + bm
        // 1) per-thread partial over its 8 cols of x3
        float wmj[8];
#pragma unroll
        for (int j = 0; j < 8; j++) wmj[j] = __ldg(&Wm[256 + n0 + j]);
        float part[8];
#pragma unroll
        for (int i = 0; i < 8; i++) {
            float p = 0.f;
#pragma unroll
            for (int j = 0; j < 8; j++) p = fmaf(acc[i][j], wmj[j], p);
            part[i] = p;
        }
        __syncthreads();                    // done reading As
        // 2) stash partials: P[n_grp][row], stride 129 (conflict-free)
        float* P = sm;                      // 16*129 floats, reuse As
        int ng = tid >> 4;
#pragma unroll
        for (int i = 0; i < 8; i++) P[ng * 129 + m0 + i] = part[i];
        __syncthreads();
        // 3) warp-per-node: x1/x2 dots + partial sum + sigmoid
        const float4* Wm4 = (const float4*)Wm;
        float4 wv1 = __ldg(&Wm4[lane]);
        float4 wv2 = __ldg(&Wm4[32 + lane]);
        float bmv = __ldg(bm);
        const float4* x1_4 = (const float4*)g_xs;
        const float4* x2_4 = (const float4*)(g_xs + (size_t)NN * DD);
#pragma unroll 1
        for (int it = 0; it < 16; it++) {
            int m = wid + it * 8;
            int node = base + m;
            if (node < NN) {
                float4 v1 = x1_4[(size_t)node * 32 + lane];
                float4 v2 = x2_4[(size_t)node * 32 + lane];
                float a = v1.x * wv1.x + v1.y * wv1.y + v1.z * wv1.z + v1.w * wv1.w
                        + v2.x * wv2.x + v2.y * wv2.y + v2.z * wv2.z + v2.w * wv2.w;
                if (lane < 16) a += P[lane * 129 + m];
#pragma unroll
                for (int o = 16; o; o >>= 1) a += __shfl_xor_sync(0xffffffffu, a, o);
                if (lane == 0) final_out[node] = 1.0f / (1.0f + expf(-(a + bmv)));
            }
        }
    }
}

// ---------------- launch ----------------
extern "C" void kernel_launch(void* const* d_in, const int* in_sizes, int n_in,
                              void* d_out, int out_size) {
    const float* x  = (const float*)d_in[0];
    const int*   ei = (const int*)d_in[1];
    const float* W1[3] = {(const float*)d_in[3],  (const float*)d_in[7],  (const float*)d_in[11]};
    const float* b1[3] = {(const float*)d_in[4],  (const float*)d_in[8],  (const float*)d_in[12]};
    const float* W2[3] = {(const float*)d_in[5],  (const float*)d_in[9],  (const float*)d_in[13]};
    const float* b2[3] = {(const float*)d_in[6],  (const float*)d_in[10], (const float*)d_in[14]};
    const float* Wm = (const float*)d_in[15];
    const float* bm = (const float*)d_in[16];
    float* out = (float*)d_out;

    const int SMEM_MLP = 3 * 128 * 128 * (int)sizeof(float);  // 192 KB
    cudaFuncSetAttribute(k_layer, cudaFuncAttributeMaxDynamicSharedMemorySize, SMEM_MLP);

    // CSR build (deterministic every launch)
    k_detect<<<1, 32>>>(ei);
    k_zero<<<(NN + 255) / 256, 256>>>();
    k_hist<<<(NE + 255) / 256, 256>>>(ei);
    k_scan1<<<NSB, SCAN_BLK>>>();
    k_scan2<<<1, 128>>>();
    k_scan3<<<NSB, SCAN_BLK>>>();
    k_scatter<<<(NE + 255) / 256, 256>>>(ei);

    const int MLP_BLOCKS = (NN + 127) / 128;        // 782
    for (int l = 0; l < 3; l++) {
        k_layer<<<MLP_BLOCKS, 256, SMEM_MLP>>>(x, W1[l], b1[l], W2[l], b2[l],
                                               Wm, bm, out, l);
    }
}

// round 6
// speedup vs baseline: 1.4830x; 1.4830x over previous
#include <cuda_runtime.h>
#include <math.h>

#define NN 100000
#define NE 1600000
#define DD 128
#define SCAN_BLK 1024
#define NSB ((NN + SCAN_BLK - 1) / SCAN_BLK)   // 98 scan blocks

// ---------------- scratch (device globals; no allocation) ----------------
__device__ alignas(16) float g_agg[(size_t)NN * DD];        // 51.2 MB
__device__ alignas(16) float g_xs[(size_t)3 * NN * DD];     // 153.6 MB
__device__ alignas(16) int   g_deg[NN];
__device__ alignas(16) int   g_cur[NN];
__device__ alignas(16) int   g_srcs[NE];
__device__ alignas(16) int   g_off[NN + 1];
__device__ alignas(16) int   g_bsum[NSB];
__device__ alignas(16) int   g_bpre[NSB];
__device__ int g_is64;

// ---------------- packed f32x2 helpers (Blackwell FFMA2) ----------------
__device__ __forceinline__ unsigned long long pk2(float x, float y) {
    unsigned long long r;
    asm("mov.b64 %0, {%1, %2};" : "=l"(r) : "f"(x), "f"(y));
    return r;
}
__device__ __forceinline__ void fma2(unsigned long long& d, unsigned long long a, unsigned long long b) {
    asm("fma.rn.f32x2 %0, %1, %2, %0;" : "+l"(d) : "l"(a), "l"(b));
}
__device__ __forceinline__ void upk2(float& x, float& y, unsigned long long v) {
    asm("mov.b64 {%0, %1}, %2;" : "=f"(x), "=f"(y) : "l"(v));
}

// ---------------- dtype probe: int32 vs int64 edge_index ----------------
__global__ void k_detect(const int* __restrict__ ei32) {
    int lane = threadIdx.x;
    int nz = 0;
#pragma unroll
    for (int i = 0; i < 2; i++) {
        int w = ei32[2 * (lane + 32 * i) + 1];
        nz |= (w != 0);
    }
    unsigned any = __ballot_sync(0xffffffffu, nz);
    if (lane == 0) g_is64 = (any == 0u) ? 1 : 0;
}

// ---------------- CSR build ----------------
__global__ void k_zero() {
    int i = blockIdx.x * blockDim.x + threadIdx.x;
    if (i < NN) g_deg[i] = 0;
}

__global__ void k_hist(const int* __restrict__ ei32) {
    int e = blockIdx.x * blockDim.x + threadIdx.x;
    if (e < NE) {
        int is64 = g_is64;
        unsigned d = is64 ? (unsigned)ei32[2 * (NE + e)] : (unsigned)ei32[NE + e];
        if (d < NN) atomicAdd(&g_deg[d], 1);
    }
}

__global__ void k_scan1() {
    __shared__ int ws[32];
    int i = blockIdx.x * SCAN_BLK + threadIdx.x;
    int v = (i < NN) ? g_deg[i] : 0;
    int s = v;
#pragma unroll
    for (int o = 16; o; o >>= 1) s += __shfl_xor_sync(0xffffffffu, s, o);
    if ((threadIdx.x & 31) == 0) ws[threadIdx.x >> 5] = s;
    __syncthreads();
    if (threadIdx.x < 32) {
        int t = ws[threadIdx.x];
#pragma unroll
        for (int o = 16; o; o >>= 1) t += __shfl_xor_sync(0xffffffffu, t, o);
        if (threadIdx.x == 0) g_bsum[blockIdx.x] = t;
    }
}

__global__ void k_scan2() {
    __shared__ int warp_incl[4];
    int t = threadIdx.x;
    int v = (t < NSB) ? g_bsum[t] : 0;
    int incl = v;
#pragma unroll
    for (int o = 1; o < 32; o <<= 1) {
        int u = __shfl_up_sync(0xffffffffu, incl, o);
        if ((t & 31) >= o) incl += u;
    }
    if ((t & 31) == 31) warp_incl[t >> 5] = incl;
    __syncthreads();
    int base = 0;
#pragma unroll
    for (int w = 0; w < 4; w++)
        if ((t >> 5) > w) base += warp_incl[w];
    incl += base;
    if (t < NSB) g_bpre[t] = incl - v;
    if (t == NSB - 1) g_off[NN] = incl;
}

__global__ void k_scan3() {
    __shared__ int s[SCAN_BLK];
    int t = threadIdx.x;
    int i = blockIdx.x * SCAN_BLK + t;
    int v = (i < NN) ? g_deg[i] : 0;
    s[t] = v;
    __syncthreads();
    for (int o = 1; o < SCAN_BLK; o <<= 1) {
        int u = (t >= o) ? s[t - o] : 0;
        __syncthreads();
        s[t] += u;
        __syncthreads();
    }
    if (i < NN) {
        int off = g_bpre[blockIdx.x] + s[t] - v;
        g_off[i] = off;
        g_cur[i] = off;
    }
}

__global__ void k_scatter(const int* __restrict__ ei32) {
    int e = blockIdx.x * blockDim.x + threadIdx.x;
    if (e < NE) {
        int is64 = g_is64;
        unsigned d    = is64 ? (unsigned)ei32[2 * (NE + e)] : (unsigned)ei32[NE + e];
        unsigned srcv = is64 ? (unsigned)ei32[2 * e]        : (unsigned)ei32[e];
        if (d < NN && srcv < NN) {
            int pos = atomicAdd(&g_cur[d], 1);
            g_srcs[pos] = (int)srcv;
        }
    }
}

// ---------------- aggregation (high occupancy, separate kernel) ----------------
__global__ void k_agg(const float* __restrict__ x0, int layer) {
    int gw = (blockIdx.x * blockDim.x + threadIdx.x) >> 5;
    if (gw >= NN) return;
    int lane = threadIdx.x & 31;
    const float* xin = (layer == 0) ? x0 : (g_xs + (size_t)(layer - 1) * NN * DD);
    const float4* x4 = (const float4*)xin;

    float4 acc = x4[(size_t)gw * 32 + lane];
    int j = g_off[gw];
    int end = g_off[gw + 1];
    for (; j + 1 < end; j += 2) {
        int s0 = g_srcs[j], s1 = g_srcs[j + 1];
        float4 a = __ldg(&x4[(size_t)s0 * 32 + lane]);
        float4 b = __ldg(&x4[(size_t)s1 * 32 + lane]);
        acc.x += a.x + b.x; acc.y += a.y + b.y;
        acc.z += a.z + b.z; acc.w += a.w + b.w;
    }
    if (j < end) {
        int s0 = g_srcs[j];
        float4 a = __ldg(&x4[(size_t)s0 * 32 + lane]);
        acc.x += a.x; acc.y += a.y; acc.z += a.z; acc.w += a.w;
    }
    ((float4*)g_agg)[(size_t)gw * 32 + lane] = acc;
}

// ---------------- fused MLP: M-tile 256, packed FFMA2, single W buffer ----------------
// As: k-major, 128 rows x 256 floats, quad-swizzled. Ws: 128x128 (W1 then W2).
__device__ __forceinline__ int swz64(int c, int k) {
    return (c ^ (c >> 3) ^ ((k >> 2) & 7)) & 63;
}

__global__ __launch_bounds__(256, 1)
void k_mlp(const float* __restrict__ W1, const float* __restrict__ b1,
           const float* __restrict__ W2, const float* __restrict__ b2,
           int layer)
{
    extern __shared__ float sm[];
    float* As = sm;                  // 128 * 256 floats = 128 KB
    float* Ws = sm + 128 * 256;      // 128 * 128 floats = 64 KB

    const int tid  = threadIdx.x;
    const int base = blockIdx.x * 256;
    const int wid  = tid >> 5;
    const int lane = tid & 31;
    const int m0 = (tid & 15) * 16;  // 16 rows per thread
    const int n0 = (tid >> 4) * 8;   // 8 cols per thread
    const int q0 = m0 >> 2;          // first quad (4 quads per thread)

    // W1 -> smem
    {
        const float4* Wg = (const float4*)W1;
        float4* Wsm = (float4*)Ws;
#pragma unroll
        for (int i = 0; i < 16; i++) Wsm[tid + i * 256] = Wg[tid + i * 256];
    }
    // A tile (g_agg) -> smem, transposed + swizzled. warp reads full 512B rows.
    {
        const float4* in4 = (const float4*)g_agg;
#pragma unroll 4
        for (int it = 0; it < 32; it++) {
            int m = wid + it * 8;            // 0..255
            int node = base + m;
            float4 v = make_float4(0.f, 0.f, 0.f, 0.f);
            if (node < NN) v = in4[(size_t)node * 32 + lane];
            int c = m >> 2, mb = m & 3;
            int k = lane * 4;
            As[(k + 0) * 256 + swz64(c, k + 0) * 4 + mb] = v.x;
            As[(k + 1) * 256 + swz64(c, k + 1) * 4 + mb] = v.y;
            As[(k + 2) * 256 + swz64(c, k + 2) * 4 + mb] = v.z;
            As[(k + 3) * 256 + swz64(c, k + 3) * 4 + mb] = v.w;
        }
    }
    __syncthreads();

    unsigned long long accp[8][8];   // [m-pair][n] packed (rows m0+2ip, m0+2ip+1)
#pragma unroll
    for (int ip = 0; ip < 8; ip++)
#pragma unroll
        for (int j = 0; j < 8; j++) accp[ip][j] = 0ull;

    // GEMM1: h = agg @ W1
    {
        const ulonglong2* As2 = (const ulonglong2*)As;
        const float4* Ws4 = (const float4*)Ws;
#pragma unroll 4
        for (int k = 0; k < 128; k++) {
            unsigned long long av[8];
#pragma unroll
            for (int ii = 0; ii < 4; ii++) {
                ulonglong2 u = As2[k * 64 + swz64(q0 + ii, k)];
                av[2 * ii] = u.x; av[2 * ii + 1] = u.y;
            }
            float4 w0 = Ws4[k * 32 + (n0 >> 2)];
            float4 w1 = Ws4[k * 32 + (n0 >> 2) + 1];
            unsigned long long wd[8] = {
                pk2(w0.x, w0.x), pk2(w0.y, w0.y), pk2(w0.z, w0.z), pk2(w0.w, w0.w),
                pk2(w1.x, w1.x), pk2(w1.y, w1.y), pk2(w1.z, w1.z), pk2(w1.w, w1.w)};
#pragma unroll
            for (int ip = 0; ip < 8; ip++)
#pragma unroll
                for (int j = 0; j < 8; j++) fma2(accp[ip][j], av[ip], wd[j]);
        }
    }

    // bias + relu, packed in place
#pragma unroll
    for (int j = 0; j < 8; j++) {
        float bj = __ldg(&b1[n0 + j]);
#pragma unroll
        for (int ip = 0; ip < 8; ip++) {
            float lo, hi;
            upk2(lo, hi, accp[ip][j]);
            lo = fmaxf(lo + bj, 0.f);
            hi = fmaxf(hi + bj, 0.f);
            accp[ip][j] = pk2(lo, hi);
        }
    }

    __syncthreads();   // all GEMM1 reads of As / Ws done
    // store h into As (k-major, swizzled); pairs along m -> ulonglong2 stores
    {
        ulonglong2* As2w = (ulonglong2*)As;
#pragma unroll
        for (int j = 0; j < 8; j++) {
            int k2 = n0 + j;
#pragma unroll
            for (int ii = 0; ii < 4; ii++) {
                ulonglong2 u;
                u.x = accp[2 * ii][j];
                u.y = accp[2 * ii + 1][j];
                As2w[k2 * 64 + swz64(q0 + ii, k2)] = u;
            }
        }
    }
    // W2 -> smem (overwrite W1)
    {
        const float4* Wg = (const float4*)W2;
        float4* Wsm = (float4*)Ws;
#pragma unroll
        for (int i = 0; i < 16; i++) Wsm[tid + i * 256] = Wg[tid + i * 256];
    }
    __syncthreads();

#pragma unroll
    for (int ip = 0; ip < 8; ip++)
#pragma unroll
        for (int j = 0; j < 8; j++) accp[ip][j] = 0ull;

    // GEMM2: out = h @ W2
    {
        const ulonglong2* As2 = (const ulonglong2*)As;
        const float4* Ws4 = (const float4*)Ws;
#pragma unroll 4
        for (int k = 0; k < 128; k++) {
            unsigned long long av[8];
#pragma unroll
            for (int ii = 0; ii < 4; ii++) {
                ulonglong2 u = As2[k * 64 + swz64(q0 + ii, k)];
                av[2 * ii] = u.x; av[2 * ii + 1] = u.y;
            }
            float4 w0 = Ws4[k * 32 + (n0 >> 2)];
            float4 w1 = Ws4[k * 32 + (n0 >> 2) + 1];
            unsigned long long wd[8] = {
                pk2(w0.x, w0.x), pk2(w0.y, w0.y), pk2(w0.z, w0.z), pk2(w0.w, w0.w),
                pk2(w1.x, w1.x), pk2(w1.y, w1.y), pk2(w1.z, w1.z), pk2(w1.w, w1.w)};
#pragma unroll
            for (int ip = 0; ip < 8; ip++)
#pragma unroll
                for (int j = 0; j < 8; j++) fma2(accp[ip][j], av[ip], wd[j]);
        }
    }

    // bias (+relu for layers 0,1), write rows to g_xs[layer]
    const int relu_out = (layer < 2);
    float bj2[8];
#pragma unroll
    for (int j = 0; j < 8; j++) bj2[j] = __ldg(&b2[n0 + j]);

    float* outbuf = g_xs + (size_t)layer * NN * DD;
    float4* out4 = (float4*)outbuf;
#pragma unroll
    for (int ip = 0; ip < 8; ip++) {
        float r0[8], r1[8];
#pragma unroll
        for (int j = 0; j < 8; j++) {
            float lo, hi;
            upk2(lo, hi, accp[ip][j]);
            lo += bj2[j]; hi += bj2[j];
            if (relu_out) { lo = fmaxf(lo, 0.f); hi = fmaxf(hi, 0.f); }
            r0[j] = lo; r1[j] = hi;
        }
        int m_lo = base + m0 + 2 * ip;
        if (m_lo < NN) {
            out4[(size_t)m_lo * 32 + (n0 >> 2)]     = make_float4(r0[0], r0[1], r0[2], r0[3]);
            out4[(size_t)m_lo * 32 + (n0 >> 2) + 1] = make_float4(r0[4], r0[5], r0[6], r0[7]);
        }
        int m_hi = m_lo + 1;
        if (m_hi < NN) {
            out4[(size_t)m_hi * 32 + (n0 >> 2)]     = make_float4(r1[0], r1[1], r1[2], r1[3]);
            out4[(size_t)m_hi * 32 + (n0 >> 2) + 1] = make_float4(r1[4], r1[5], r1[6], r1[7]);
        }
    }
}

// ---------------- readout ----------------
__global__ void k_readout(const float* __restrict__ Wm, const float* __restrict__ bm,
                          float* __restrict__ out) {
    int gw = (blockIdx.x * blockDim.x + threadIdx.x) >> 5;
    if (gw >= NN) return;
    int lane = threadIdx.x & 31;
    float acc = 0.f;
#pragma unroll
    for (int l = 0; l < 3; l++) {
        const float4* xs4 = (const float4*)(g_xs + (size_t)l * NN * DD);
        float4 v = xs4[(size_t)gw * 32 + lane];
        float4 w = __ldg(&((const float4*)Wm)[l * 32 + lane]);
        acc += v.x * w.x + v.y * w.y + v.z * w.z + v.w * w.w;
    }
#pragma unroll
    for (int o = 16; o; o >>= 1) acc += __shfl_xor_sync(0xffffffffu, acc, o);
    if (lane == 0) {
        float z = acc + __ldg(bm);
        out[gw] = 1.0f / (1.0f + expf(-z));
    }
}

// ---------------- launch ----------------
extern "C" void kernel_launch(void* const* d_in, const int* in_sizes, int n_in,
                              void* d_out, int out_size) {
    const float* x  = (const float*)d_in[0];
    const int*   ei = (const int*)d_in[1];
    const float* W1[3] = {(const float*)d_in[3],  (const float*)d_in[7],  (const float*)d_in[11]};
    const float* b1[3] = {(const float*)d_in[4],  (const float*)d_in[8],  (const float*)d_in[12]};
    const float* W2[3] = {(const float*)d_in[5],  (const float*)d_in[9],  (const float*)d_in[13]};
    const float* b2[3] = {(const float*)d_in[6],  (const float*)d_in[10], (const float*)d_in[14]};
    const float* Wm = (const float*)d_in[15];
    const float* bm = (const float*)d_in[16];
    float* out = (float*)d_out;

    const int SMEM_MLP = (128 * 256 + 128 * 128) * (int)sizeof(float);  // 192 KB
    cudaFuncSetAttribute(k_mlp, cudaFuncAttributeMaxDynamicSharedMemorySize, SMEM_MLP);

    // CSR build (deterministic every launch)
    k_detect<<<1, 32>>>(ei);
    k_zero<<<(NN + 255) / 256, 256>>>();
    k_hist<<<(NE + 255) / 256, 256>>>(ei);
    k_scan1<<<NSB, SCAN_BLK>>>();
    k_scan2<<<1, 128>>>();
    k_scan3<<<NSB, SCAN_BLK>>>();
    k_scatter<<<(NE + 255) / 256, 256>>>(ei);

    const int AGG_BLOCKS = (NN * 32 + 255) / 256;   // 12500
    const int MLP_BLOCKS = (NN + 255) / 256;        // 391

    for (int l = 0; l < 3; l++) {
        k_agg<<<AGG_BLOCKS, 256>>>(x, l);
        k_mlp<<<MLP_BLOCKS, 256, SMEM_MLP>>>(W1[l], b1[l], W2[l], b2[l], l);
    }
    k_readout<<<AGG_BLOCKS, 256>>>(Wm, bm, out);
}

// round 9
// speedup vs baseline: 1.9849x; 1.3384x over previous
#include <cuda_runtime.h>
#include <cuda_bf16.h>
#include <stdint.h>
#include <math.h>

#define NN 100000
#define NE 1600000
#define DD 128
#define SCAN_BLK 1024
#define NSB ((NN + SCAN_BLK - 1) / SCAN_BLK)   // 98 scan blocks

// ---------------- scratch (device globals; no allocation) ----------------
__device__ alignas(16) float g_agg[(size_t)NN * DD];        // 51.2 MB
__device__ alignas(16) float g_xs[(size_t)3 * NN * DD];     // 153.6 MB
__device__ alignas(16) __nv_bfloat16 g_wb[6 * 128 * 256];   // split weights [mat][n][k: hi0-127|lo128-255]
__device__ alignas(16) int   g_deg[NN];
__device__ alignas(16) int   g_cur[NN];
__device__ alignas(16) int   g_srcs[NE];
__device__ alignas(16) int   g_off[NN + 1];
__device__ alignas(16) int   g_bsum[NSB];
__device__ alignas(16) int   g_bpre[NSB];
__device__ int g_is64;

__device__ __forceinline__ uint32_t smem_u32(const void* p) {
    uint32_t a;
    asm("{ .reg .u64 t; cvta.to.shared.u64 t, %1; cvt.u32.u64 %0, t; }" : "=r"(a) : "l"(p));
    return a;
}
__device__ __forceinline__ uint32_t pack_bf16(float a, float b) {
    __nv_bfloat16 ha = __float2bfloat16(a), hb = __float2bfloat16(b);
    return (uint32_t)__bfloat16_as_ushort(ha) | ((uint32_t)__bfloat16_as_ushort(hb) << 16);
}
__device__ __forceinline__ void ldsm4(uint32_t& r0, uint32_t& r1, uint32_t& r2, uint32_t& r3, uint32_t addr) {
    asm volatile("ldmatrix.sync.aligned.m8n8.x4.shared.b16 {%0,%1,%2,%3}, [%4];"
                 : "=r"(r0), "=r"(r1), "=r"(r2), "=r"(r3) : "r"(addr));
}
__device__ __forceinline__ void mma16816(float* c, const uint32_t* a, const uint32_t* b) {
    asm volatile("mma.sync.aligned.m16n8k16.row.col.f32.bf16.bf16.f32 "
                 "{%0,%1,%2,%3}, {%4,%5,%6,%7}, {%8,%9}, {%0,%1,%2,%3};"
                 : "+f"(c[0]), "+f"(c[1]), "+f"(c[2]), "+f"(c[3])
                 : "r"(a[0]), "r"(a[1]), "r"(a[2]), "r"(a[3]), "r"(b[0]), "r"(b[1]));
}
// swizzled smem byte offset within a 512B bf16 row (k: hi bytes 0-255, lo 256-511)
__device__ __forceinline__ uint32_t sws(int row, int kb) {
    return (uint32_t)(row * 512 + (kb ^ ((row & 7) << 4)));
}

// ---------------- dtype probe ----------------
__global__ void k_detect(const int* __restrict__ ei32) {
    int lane = threadIdx.x;
    int nz = 0;
#pragma unroll
    for (int i = 0; i < 2; i++) {
        int w = ei32[2 * (lane + 32 * i) + 1];
        nz |= (w != 0);
    }
    unsigned any = __ballot_sync(0xffffffffu, nz);
    if (lane == 0) g_is64 = (any == 0u) ? 1 : 0;
}

// ---------------- CSR build ----------------
__global__ void k_zero() {
    int i = blockIdx.x * blockDim.x + threadIdx.x;
    if (i < NN) g_deg[i] = 0;
}
__global__ void k_hist(const int* __restrict__ ei32) {
    int e = blockIdx.x * blockDim.x + threadIdx.x;
    if (e < NE) {
        int is64 = g_is64;
        unsigned d = is64 ? (unsigned)ei32[2 * (NE + e)] : (unsigned)ei32[NE + e];
        if (d < NN) atomicAdd(&g_deg[d], 1);
    }
}
__global__ void k_scan1() {
    __shared__ int ws[32];
    int i = blockIdx.x * SCAN_BLK + threadIdx.x;
    int v = (i < NN) ? g_deg[i] : 0;
    int s = v;
#pragma unroll
    for (int o = 16; o; o >>= 1) s += __shfl_xor_sync(0xffffffffu, s, o);
    if ((threadIdx.x & 31) == 0) ws[threadIdx.x >> 5] = s;
    __syncthreads();
    if (threadIdx.x < 32) {
        int t = ws[threadIdx.x];
#pragma unroll
        for (int o = 16; o; o >>= 1) t += __shfl_xor_sync(0xffffffffu, t, o);
        if (threadIdx.x == 0) g_bsum[blockIdx.x] = t;
    }
}
__global__ void k_scan2() {
    __shared__ int warp_incl[4];
    int t = threadIdx.x;
    int v = (t < NSB) ? g_bsum[t] : 0;
    int incl = v;
#pragma unroll
    for (int o = 1; o < 32; o <<= 1) {
        int u = __shfl_up_sync(0xffffffffu, incl, o);
        if ((t & 31) >= o) incl += u;
    }
    if ((t & 31) == 31) warp_incl[t >> 5] = incl;
    __syncthreads();
    int base = 0;
#pragma unroll
    for (int w = 0; w < 4; w++)
        if ((t >> 5) > w) base += warp_incl[w];
    incl += base;
    if (t < NSB) g_bpre[t] = incl - v;
    if (t == NSB - 1) g_off[NN] = incl;
}
__global__ void k_scan3() {
    __shared__ int s[SCAN_BLK];
    int t = threadIdx.x;
    int i = blockIdx.x * SCAN_BLK + t;
    int v = (i < NN) ? g_deg[i] : 0;
    s[t] = v;
    __syncthreads();
    for (int o = 1; o < SCAN_BLK; o <<= 1) {
        int u = (t >= o) ? s[t - o] : 0;
        __syncthreads();
        s[t] += u;
        __syncthreads();
    }
    if (i < NN) {
        int off = g_bpre[blockIdx.x] + s[t] - v;
        g_off[i] = off;
        g_cur[i] = off;
    }
}
__global__ void k_scatter(const int* __restrict__ ei32) {
    int e = blockIdx.x * blockDim.x + threadIdx.x;
    if (e < NE) {
        int is64 = g_is64;
        unsigned d    = is64 ? (unsigned)ei32[2 * (NE + e)] : (unsigned)ei32[NE + e];
        unsigned srcv = is64 ? (unsigned)ei32[2 * e]        : (unsigned)ei32[e];
        if (d < NN && srcv < NN) {
            int pos = atomicAdd(&g_cur[d], 1);
            g_srcs[pos] = (int)srcv;
        }
    }
}

// ---------------- weight prep: W[k][n] fp32 -> bf16 hi/lo transposed [n][hi(k)|lo(k)] ----------------
__global__ void k_wprep(const float* __restrict__ w0, const float* __restrict__ w1,
                        const float* __restrict__ w2, const float* __restrict__ w3,
                        const float* __restrict__ w4, const float* __restrict__ w5) {
    int idx = blockIdx.x * blockDim.x + threadIdx.x;   // 6*128*128
    if (idx >= 6 * 128 * 128) return;
    int mat = idx >> 14;
    int k = (idx >> 7) & 127;
    int n = idx & 127;
    const float* W = (mat == 0) ? w0 : (mat == 1) ? w1 : (mat == 2) ? w2
                   : (mat == 3) ? w3 : (mat == 4) ? w4 : w5;
    float v = W[k * 128 + n];
    __nv_bfloat16 hi = __float2bfloat16(v);
    __nv_bfloat16 lo = __float2bfloat16(v - __bfloat162float(hi));
    __nv_bfloat16* dst = g_wb + (size_t)mat * 128 * 256 + (size_t)n * 256;
    dst[k] = hi;
    dst[128 + k] = lo;
}

// ---------------- aggregation ----------------
__global__ void k_agg(const float* __restrict__ x0, int layer) {
    int gw = (blockIdx.x * blockDim.x + threadIdx.x) >> 5;
    if (gw >= NN) return;
    int lane = threadIdx.x & 31;
    const float* xin = (layer == 0) ? x0 : (g_xs + (size_t)(layer - 1) * NN * DD);
    const float4* x4 = (const float4*)xin;

    float4 acc = x4[(size_t)gw * 32 + lane];
    int j = g_off[gw];
    int end = g_off[gw + 1];
    for (; j + 1 < end; j += 2) {
        int s0 = g_srcs[j], s1 = g_srcs[j + 1];
        float4 a = __ldg(&x4[(size_t)s0 * 32 + lane]);
        float4 b = __ldg(&x4[(size_t)s1 * 32 + lane]);
        acc.x += a.x + b.x; acc.y += a.y + b.y;
        acc.z += a.z + b.z; acc.w += a.w + b.w;
    }
    if (j < end) {
        int s0 = g_srcs[j];
        float4 a = __ldg(&x4[(size_t)s0 * 32 + lane]);
        acc.x += a.x; acc.y += a.y; acc.z += a.z; acc.w += a.w;
    }
    ((float4*)g_agg)[(size_t)gw * 32 + lane] = acc;
}

// ---------------- mma.sync bf16 MLP: 128x128 tile per CTA ----------------
// smem: A @0 (128 rows x 512B = 64KB), W1 @65536 (64KB), W2 @131072 (64KB)
#define SW1_OFF 65536u
#define SW2_OFF 131072u
#define SMEM_MLP 196608

__global__ __launch_bounds__(256)
void k_mlp(const float* __restrict__ b1, const float* __restrict__ b2, int layer)
{
    extern __shared__ char smem[];
    const uint32_t sa = smem_u32(smem);
    const int tid = threadIdx.x, wid = tid >> 5, lane = tid & 31;
    const int base = blockIdx.x * 128;
    const int wm = wid & 3, wn = wid >> 2;
    const int m0w = wm * 32;            // warp's 32 rows
    const int ncol0 = wn * 64;          // warp's 64 cols
    const int lr = lane & 7, grp = lane >> 3;
    const __nv_bfloat16* wb1 = g_wb + (size_t)(layer * 2)     * 128 * 256;
    const __nv_bfloat16* wb2 = g_wb + (size_t)(layer * 2 + 1) * 128 * 256;

    // ---- build A (split hi/lo) ----
    {
        const float4* in4 = (const float4*)g_agg;
        int kb = lane * 8;      // hi bytes for 4 k-elems
#pragma unroll 4
        for (int it = 0; it < 16; it++) {
            int m = wid + it * 8;
            int node = base + m;
            float4 v = make_float4(0.f, 0.f, 0.f, 0.f);
            if (node < NN) v = in4[(size_t)node * 32 + lane];
            float hx = __bfloat162float(__float2bfloat16(v.x));
            float hy = __bfloat162float(__float2bfloat16(v.y));
            float hz = __bfloat162float(__float2bfloat16(v.z));
            float hw = __bfloat162float(__float2bfloat16(v.w));
            uint2 hi = make_uint2(pack_bf16(v.x, v.y), pack_bf16(v.z, v.w));
            uint2 lo = make_uint2(pack_bf16(v.x - hx, v.y - hy), pack_bf16(v.z - hz, v.w - hw));
            *(uint2*)(smem + sws(m, kb))       = hi;
            *(uint2*)(smem + sws(m, 256 + kb)) = lo;
        }
    }
    // ---- load W1/W2 into swizzled smem ----
    {
        int kb = lane * 16;
#pragma unroll 4
        for (int it = 0; it < 16; it++) {
            int n = wid + it * 8;
            uint4 r1 = ((const uint4*)(wb1 + (size_t)n * 256))[lane];
            uint4 r2 = ((const uint4*)(wb2 + (size_t)n * 256))[lane];
            uint32_t o = sws(n, kb);
            *(uint4*)(smem + SW1_OFF + o) = r1;
            *(uint4*)(smem + SW2_OFF + o) = r2;
        }
    }
    __syncthreads();

    // per-lane ldmatrix address components
    const int arow = lr + ((grp & 1) << 3);   // A: tiles (m,klo),(m+8,klo),(m,khi),(m+8,khi)
    const int akadd = (grp & 2) ? 16 : 0;
    const int brow = lr + ((grp & 2) << 2);   // B: tiles (n,klo),(n,khi),(n+8,klo),(n+8,khi)
    const int bkadd = (grp & 1) ? 16 : 0;
    const uint32_t lxor = (uint32_t)(lr << 4);
    uint32_t abase[2], bbase[4];
#pragma unroll
    for (int i = 0; i < 2; i++) abase[i] = sa + (uint32_t)((m0w + 16 * i + arow) * 512);
#pragma unroll
    for (int j = 0; j < 4; j++) bbase[j] = (uint32_t)((ncol0 + 16 * j + brow) * 512);

    float c[2][8][4];

    // ================= two GEMMs =================
#pragma unroll 1
    for (int g = 0; g < 2; g++) {
        const uint32_t woff = sa + (g == 0 ? SW1_OFF : SW2_OFF);
#pragma unroll
        for (int i = 0; i < 2; i++)
#pragma unroll
            for (int j = 0; j < 8; j++)
#pragma unroll
                for (int q = 0; q < 4; q++) c[i][j][q] = 0.f;

        // 3 split terms x 8 k-steps
#pragma unroll 1
        for (int t = 0; t < 3; t++) {
            const int akoff = (t == 2) ? 256 : 0;
            const int bkoff = (t == 1) ? 256 : 0;
#pragma unroll
            for (int ks = 0; ks < 8; ks++) {
                const int kb = ks * 32;
                uint32_t fa[2][4], fb[8][2];
#pragma unroll
                for (int i = 0; i < 2; i++)
                    ldsm4(fa[i][0], fa[i][1], fa[i][2], fa[i][3],
                          abase[i] + (uint32_t)((kb + akoff + akadd) ^ lxor));
#pragma unroll
                for (int jj = 0; jj < 4; jj++) {
                    uint32_t r0, r1, r2, r3;
                    ldsm4(r0, r1, r2, r3,
                          woff + bbase[jj] + (uint32_t)((kb + bkoff + bkadd) ^ lxor));
                    fb[2 * jj][0] = r0; fb[2 * jj][1] = r1;
                    fb[2 * jj + 1][0] = r2; fb[2 * jj + 1][1] = r3;
                }
#pragma unroll
                for (int i = 0; i < 2; i++)
#pragma unroll
                    for (int j = 0; j < 8; j++)
                        mma16816(c[i][j], fa[i], fb[j]);
            }
        }

        if (g == 0) {
            // epilogue 1: bias+relu, split h back into A smem
            __syncthreads();   // all warps done reading A
#pragma unroll
            for (int j = 0; j < 8; j++) {
                int n = ncol0 + 8 * j + 2 * (lane & 3);
                float bn0 = __ldg(&b1[n]), bn1 = __ldg(&b1[n + 1]);
#pragma unroll
                for (int i = 0; i < 2; i++) {
                    int r0 = m0w + 16 * i + (lane >> 2);
                    float h0 = fmaxf(c[i][j][0] + bn0, 0.f);
                    float h1 = fmaxf(c[i][j][1] + bn1, 0.f);
                    float h2 = fmaxf(c[i][j][2] + bn0, 0.f);
                    float h3 = fmaxf(c[i][j][3] + bn1, 0.f);
                    float t0 = __bfloat162float(__float2bfloat16(h0));
                    float t1 = __bfloat162float(__float2bfloat16(h1));
                    float t2 = __bfloat162float(__float2bfloat16(h2));
                    float t3 = __bfloat162float(__float2bfloat16(h3));
                    *(uint32_t*)(smem + sws(r0, 2 * n))           = pack_bf16(h0, h1);
                    *(uint32_t*)(smem + sws(r0, 256 + 2 * n))     = pack_bf16(h0 - t0, h1 - t1);
                    *(uint32_t*)(smem + sws(r0 + 8, 2 * n))       = pack_bf16(h2, h3);
                    *(uint32_t*)(smem + sws(r0 + 8, 256 + 2 * n)) = pack_bf16(h2 - t2, h3 - t3);
                }
            }
            __syncthreads();
        }
    }

    // ---- epilogue 2: bias (+relu), write g_xs[layer] ----
    {
        const int relu_out = (layer < 2);
        float* outp = g_xs + (size_t)layer * NN * DD;
#pragma unroll
        for (int j = 0; j < 8; j++) {
            int n = ncol0 + 8 * j + 2 * (lane & 3);
            float bn0 = __ldg(&b2[n]), bn1 = __ldg(&b2[n + 1]);
#pragma unroll
            for (int i = 0; i < 2; i++) {
                int r0 = base + m0w + 16 * i + (lane >> 2);
                float o0 = c[i][j][0] + bn0, o1 = c[i][j][1] + bn1;
                float o2 = c[i][j][2] + bn0, o3 = c[i][j][3] + bn1;
                if (relu_out) {
                    o0 = fmaxf(o0, 0.f); o1 = fmaxf(o1, 0.f);
                    o2 = fmaxf(o2, 0.f); o3 = fmaxf(o3, 0.f);
                }
                if (r0 < NN)     *(float2*)(outp + (size_t)r0 * DD + n)       = make_float2(o0, o1);
                if (r0 + 8 < NN) *(float2*)(outp + (size_t)(r0 + 8) * DD + n) = make_float2(o2, o3);
            }
        }
    }
}

// ---------------- readout ----------------
__global__ void k_readout(const float* __restrict__ Wm, const float* __restrict__ bm,
                          float* __restrict__ out) {
    int gw = (blockIdx.x * blockDim.x + threadIdx.x) >> 5;
    if (gw >= NN) return;
    int lane = threadIdx.x & 31;
    float acc = 0.f;
#pragma unroll
    for (int l = 0; l < 3; l++) {
        const float4* xs4 = (const float4*)(g_xs + (size_t)l * NN * DD);
        float4 v = xs4[(size_t)gw * 32 + lane];
        float4 w = __ldg(&((const float4*)Wm)[l * 32 + lane]);
        acc += v.x * w.x + v.y * w.y + v.z * w.z + v.w * w.w;
    }
#pragma unroll
    for (int o = 16; o; o >>= 1) acc += __shfl_xor_sync(0xffffffffu, acc, o);
    if (lane == 0) {
        float z = acc + __ldg(bm);
        out[gw] = 1.0f / (1.0f + expf(-z));
    }
}

// ---------------- launch ----------------
extern "C" void kernel_launch(void* const* d_in, const int* in_sizes, int n_in,
                              void* d_out, int out_size) {
    const float* x  = (const float*)d_in[0];
    const int*   ei = (const int*)d_in[1];
    const float* W1[3] = {(const float*)d_in[3],  (const float*)d_in[7],  (const float*)d_in[11]};
    const float* b1[3] = {(const float*)d_in[4],  (const float*)d_in[8],  (const float*)d_in[12]};
    const float* W2[3] = {(const float*)d_in[5],  (const float*)d_in[9],  (const float*)d_in[13]};
    const float* b2[3] = {(const float*)d_in[6],  (const float*)d_in[10], (const float*)d_in[14]};
    const float* Wm = (const float*)d_in[15];
    const float* bm = (const float*)d_in[16];
    float* out = (float*)d_out;

    cudaFuncSetAttribute(k_mlp, cudaFuncAttributeMaxDynamicSharedMemorySize, SMEM_MLP);

    // CSR build + weight prep (deterministic every launch)
    k_detect<<<1, 32>>>(ei);
    k_zero<<<(NN + 255) / 256, 256>>>();
    k_hist<<<(NE + 255) / 256, 256>>>(ei);
    k_scan1<<<NSB, SCAN_BLK>>>();
    k_scan2<<<1, 128>>>();
    k_scan3<<<NSB, SCAN_BLK>>>();
    k_scatter<<<(NE + 255) / 256, 256>>>(ei);
    k_wprep<<<(6 * 128 * 128 + 255) / 256, 256>>>(W1[0], W2[0], W1[1], W2[1], W1[2], W2[2]);

    const int AGG_BLOCKS = (NN * 32 + 255) / 256;   // 12500
    const int MLP_BLOCKS = (NN + 127) / 128;        // 782

    for (int l = 0; l < 3; l++) {
        k_agg<<<AGG_BLOCKS, 256>>>(x, l);
        k_mlp<<<MLP_BLOCKS, 256, SMEM_MLP>>>(b1[l], b2[l], l);
    }
    k_readout<<<AGG_BLOCKS, 256>>>(Wm, bm, out);
}

// round 10
// speedup vs baseline: 2.1461x; 1.0812x over previous
#include <cuda_runtime.h>
#include <cuda_bf16.h>
#include <cuda_fp16.h>
#include <stdint.h>
#include <math.h>

#define NN 100000
#define NE 1600000
#define DD 128
#define SCAN_BLK 1024
#define NSB ((NN + SCAN_BLK - 1) / SCAN_BLK)   // 98 scan blocks

// ---------------- scratch (device globals; no allocation) ----------------
__device__ alignas(16) float  g_agg[(size_t)NN * DD];         // 51.2 MB (fp32 MLP input)
__device__ alignas(16) __half g_x16[(size_t)NN * DD];         // 25.6 MB (fp16 input copy)
__device__ alignas(16) __half g_xs16[(size_t)3 * NN * DD];    // 76.8 MB (fp16 layer outputs)
__device__ alignas(16) __nv_bfloat16 g_wb[6 * 128 * 256];     // split weights [mat][n][k: hi|lo]
__device__ alignas(16) int   g_deg[NN];
__device__ alignas(16) int   g_cur[NN];
__device__ alignas(16) int   g_srcs[NE];
__device__ alignas(16) int   g_off[NN + 1];
__device__ alignas(16) int   g_bsum[NSB];
__device__ alignas(16) int   g_bpre[NSB];
__device__ int g_is64;

__device__ __forceinline__ uint32_t smem_u32(const void* p) {
    uint32_t a;
    asm("{ .reg .u64 t; cvta.to.shared.u64 t, %1; cvt.u32.u64 %0, t; }" : "=r"(a) : "l"(p));
    return a;
}
__device__ __forceinline__ uint32_t pack_bf16(float a, float b) {
    __nv_bfloat16 ha = __float2bfloat16(a), hb = __float2bfloat16(b);
    return (uint32_t)__bfloat16_as_ushort(ha) | ((uint32_t)__bfloat16_as_ushort(hb) << 16);
}
__device__ __forceinline__ void ldsm4(uint32_t& r0, uint32_t& r1, uint32_t& r2, uint32_t& r3, uint32_t addr) {
    asm volatile("ldmatrix.sync.aligned.m8n8.x4.shared.b16 {%0,%1,%2,%3}, [%4];"
                 : "=r"(r0), "=r"(r1), "=r"(r2), "=r"(r3) : "r"(addr));
}
__device__ __forceinline__ void mma16816(float* c, const uint32_t* a, const uint32_t* b) {
    asm volatile("mma.sync.aligned.m16n8k16.row.col.f32.bf16.bf16.f32 "
                 "{%0,%1,%2,%3}, {%4,%5,%6,%7}, {%8,%9}, {%0,%1,%2,%3};"
                 : "+f"(c[0]), "+f"(c[1]), "+f"(c[2]), "+f"(c[3])
                 : "r"(a[0]), "r"(a[1]), "r"(a[2]), "r"(a[3]), "r"(b[0]), "r"(b[1]));
}
// swizzled smem byte offset within a 512B bf16 row (k: hi bytes 0-255, lo 256-511)
__device__ __forceinline__ uint32_t sws(int row, int kb) {
    return (uint32_t)(row * 512 + (kb ^ ((row & 7) << 4)));
}
// unpack 4 packed halves (uint2) -> float4
__device__ __forceinline__ float4 h4tof4(uint2 u) {
    __half2 h0 = *(__half2*)&u.x, h1 = *(__half2*)&u.y;
    float2 f0 = __half22float2(h0), f1 = __half22float2(h1);
    return make_float4(f0.x, f0.y, f1.x, f1.y);
}

// ---------------- dtype probe ----------------
__global__ void k_detect(const int* __restrict__ ei32) {
    int lane = threadIdx.x;
    int nz = 0;
#pragma unroll
    for (int i = 0; i < 2; i++) {
        int w = ei32[2 * (lane + 32 * i) + 1];
        nz |= (w != 0);
    }
    unsigned any = __ballot_sync(0xffffffffu, nz);
    if (lane == 0) g_is64 = (any == 0u) ? 1 : 0;
}

// ---------------- input fp32 -> fp16 ----------------
__global__ void k_xprep(const float* __restrict__ x) {
    int i = blockIdx.x * blockDim.x + threadIdx.x;   // over NN*DD/4
    if (i < NN * DD / 4) {
        float4 v = ((const float4*)x)[i];
        __half2 a = __floats2half2_rn(v.x, v.y);
        __half2 b = __floats2half2_rn(v.z, v.w);
        ((__half2*)g_x16)[2 * i]     = a;
        ((__half2*)g_x16)[2 * i + 1] = b;
    }
}

// ---------------- CSR build ----------------
__global__ void k_zero() {
    int i = blockIdx.x * blockDim.x + threadIdx.x;
    if (i < NN) g_deg[i] = 0;
}
__global__ void k_hist(const int* __restrict__ ei32) {
    int e = blockIdx.x * blockDim.x + threadIdx.x;
    if (e < NE) {
        int is64 = g_is64;
        unsigned d = is64 ? (unsigned)ei32[2 * (NE + e)] : (unsigned)ei32[NE + e];
        if (d < NN) atomicAdd(&g_deg[d], 1);
    }
}
__global__ void k_scan1() {
    __shared__ int ws[32];
    int i = blockIdx.x * SCAN_BLK + threadIdx.x;
    int v = (i < NN) ? g_deg[i] : 0;
    int s = v;
#pragma unroll
    for (int o = 16; o; o >>= 1) s += __shfl_xor_sync(0xffffffffu, s, o);
    if ((threadIdx.x & 31) == 0) ws[threadIdx.x >> 5] = s;
    __syncthreads();
    if (threadIdx.x < 32) {
        int t = ws[threadIdx.x];
#pragma unroll
        for (int o = 16; o; o >>= 1) t += __shfl_xor_sync(0xffffffffu, t, o);
        if (threadIdx.x == 0) g_bsum[blockIdx.x] = t;
    }
}
__global__ void k_scan2() {
    __shared__ int warp_incl[4];
    int t = threadIdx.x;
    int v = (t < NSB) ? g_bsum[t] : 0;
    int incl = v;
#pragma unroll
    for (int o = 1; o < 32; o <<= 1) {
        int u = __shfl_up_sync(0xffffffffu, incl, o);
        if ((t & 31) >= o) incl += u;
    }
    if ((t & 31) == 31) warp_incl[t >> 5] = incl;
    __syncthreads();
    int base = 0;
#pragma unroll
    for (int w = 0; w < 4; w++)
        if ((t >> 5) > w) base += warp_incl[w];
    incl += base;
    if (t < NSB) g_bpre[t] = incl - v;
    if (t == NSB - 1) g_off[NN] = incl;
}
__global__ void k_scan3() {
    __shared__ int s[SCAN_BLK];
    int t = threadIdx.x;
    int i = blockIdx.x * SCAN_BLK + t;
    int v = (i < NN) ? g_deg[i] : 0;
    s[t] = v;
    __syncthreads();
    for (int o = 1; o < SCAN_BLK; o <<= 1) {
        int u = (t >= o) ? s[t - o] : 0;
        __syncthreads();
        s[t] += u;
        __syncthreads();
    }
    if (i < NN) {
        int off = g_bpre[blockIdx.x] + s[t] - v;
        g_off[i] = off;
        g_cur[i] = off;
    }
}
__global__ void k_scatter(const int* __restrict__ ei32) {
    int e = blockIdx.x * blockDim.x + threadIdx.x;
    if (e < NE) {
        int is64 = g_is64;
        unsigned d    = is64 ? (unsigned)ei32[2 * (NE + e)] : (unsigned)ei32[NE + e];
        unsigned srcv = is64 ? (unsigned)ei32[2 * e]        : (unsigned)ei32[e];
        if (d < NN && srcv < NN) {
            int pos = atomicAdd(&g_cur[d], 1);
            g_srcs[pos] = (int)srcv;
        }
    }
}

// ---------------- weight prep: W[k][n] fp32 -> bf16 hi/lo transposed [n][hi(k)|lo(k)] ----------------
__global__ void k_wprep(const float* __restrict__ w0, const float* __restrict__ w1,
                        const float* __restrict__ w2, const float* __restrict__ w3,
                        const float* __restrict__ w4, const float* __restrict__ w5) {
    int idx = blockIdx.x * blockDim.x + threadIdx.x;   // 6*128*128
    if (idx >= 6 * 128 * 128) return;
    int mat = idx >> 14;
    int k = (idx >> 7) & 127;
    int n = idx & 127;
    const float* W = (mat == 0) ? w0 : (mat == 1) ? w1 : (mat == 2) ? w2
                   : (mat == 3) ? w3 : (mat == 4) ? w4 : w5;
    float v = W[k * 128 + n];
    __nv_bfloat16 hi = __float2bfloat16(v);
    __nv_bfloat16 lo = __float2bfloat16(v - __bfloat162float(hi));
    __nv_bfloat16* dst = g_wb + (size_t)mat * 128 * 256 + (size_t)n * 256;
    dst[k] = hi;
    dst[128 + k] = lo;
}

// ---------------- aggregation: fp16 gather (256B rows), fp32 accumulate ----------------
__global__ void k_agg(int layer) {
    int gw = (blockIdx.x * blockDim.x + threadIdx.x) >> 5;
    if (gw >= NN) return;
    int lane = threadIdx.x & 31;
    const __half* xin = (layer == 0) ? g_x16 : (g_xs16 + (size_t)(layer - 1) * NN * DD);
    const uint2* x2 = (const uint2*)xin;   // 4 halves per lane, 32 lanes = 256B row

    float4 acc = h4tof4(x2[(size_t)gw * 32 + lane]);
    int j = g_off[gw];
    int end = g_off[gw + 1];
    for (; j + 1 < end; j += 2) {
        int s0 = g_srcs[j], s1 = g_srcs[j + 1];
        float4 a = h4tof4(__ldg(&x2[(size_t)s0 * 32 + lane]));
        float4 b = h4tof4(__ldg(&x2[(size_t)s1 * 32 + lane]));
        acc.x += a.x + b.x; acc.y += a.y + b.y;
        acc.z += a.z + b.z; acc.w += a.w + b.w;
    }
    if (j < end) {
        float4 a = h4tof4(__ldg(&x2[(size_t)g_srcs[j] * 32 + lane]));
        acc.x += a.x; acc.y += a.y; acc.z += a.z; acc.w += a.w;
    }
    ((float4*)g_agg)[(size_t)gw * 32 + lane] = acc;
}

// ---------------- mma.sync bf16 MLP: 128x128 tile per CTA ----------------
// smem: A @0 (128 rows x 512B = 64KB), W1 @65536 (64KB), W2 @131072 (64KB)
#define SW1_OFF 65536u
#define SW2_OFF 131072u
#define SMEM_MLP 196608

__global__ __launch_bounds__(256)
void k_mlp(const float* __restrict__ b1, const float* __restrict__ b2, int layer)
{
    extern __shared__ char smem[];
    const uint32_t sa = smem_u32(smem);
    const int tid = threadIdx.x, wid = tid >> 5, lane = tid & 31;
    const int base = blockIdx.x * 128;
    const int wm = wid & 3, wn = wid >> 2;
    const int m0w = wm * 32;            // warp's 32 rows
    const int ncol0 = wn * 64;          // warp's 64 cols
    const int lr = lane & 7, grp = lane >> 3;
    const __nv_bfloat16* wb1 = g_wb + (size_t)(layer * 2)     * 128 * 256;
    const __nv_bfloat16* wb2 = g_wb + (size_t)(layer * 2 + 1) * 128 * 256;

    // ---- build A (split hi/lo) from fp32 g_agg ----
    {
        const float4* in4 = (const float4*)g_agg;
        int kb = lane * 8;
#pragma unroll 4
        for (int it = 0; it < 16; it++) {
            int m = wid + it * 8;
            int node = base + m;
            float4 v = make_float4(0.f, 0.f, 0.f, 0.f);
            if (node < NN) v = in4[(size_t)node * 32 + lane];
            float hx = __bfloat162float(__float2bfloat16(v.x));
            float hy = __bfloat162float(__float2bfloat16(v.y));
            float hz = __bfloat162float(__float2bfloat16(v.z));
            float hw = __bfloat162float(__float2bfloat16(v.w));
            uint2 hi = make_uint2(pack_bf16(v.x, v.y), pack_bf16(v.z, v.w));
            uint2 lo = make_uint2(pack_bf16(v.x - hx, v.y - hy), pack_bf16(v.z - hz, v.w - hw));
            *(uint2*)(smem + sws(m, kb))       = hi;
            *(uint2*)(smem + sws(m, 256 + kb)) = lo;
        }
    }
    // ---- load W1/W2 into swizzled smem ----
    {
        int kb = lane * 16;
#pragma unroll 4
        for (int it = 0; it < 16; it++) {
            int n = wid + it * 8;
            uint4 r1 = ((const uint4*)(wb1 + (size_t)n * 256))[lane];
            uint4 r2 = ((const uint4*)(wb2 + (size_t)n * 256))[lane];
            uint32_t o = sws(n, kb);
            *(uint4*)(smem + SW1_OFF + o) = r1;
            *(uint4*)(smem + SW2_OFF + o) = r2;
        }
    }
    __syncthreads();

    const int arow = lr + ((grp & 1) << 3);
    const int akadd = (grp & 2) ? 16 : 0;
    const int brow = lr + ((grp & 2) << 2);
    const int bkadd = (grp & 1) ? 16 : 0;
    const uint32_t lxor = (uint32_t)(lr << 4);
    uint32_t abase[2], bbase[4];
#pragma unroll
    for (int i = 0; i < 2; i++) abase[i] = sa + (uint32_t)((m0w + 16 * i + arow) * 512);
#pragma unroll
    for (int j = 0; j < 4; j++) bbase[j] = (uint32_t)((ncol0 + 16 * j + brow) * 512);

    float c[2][8][4];

#pragma unroll 1
    for (int g = 0; g < 2; g++) {
        const uint32_t woff = sa + (g == 0 ? SW1_OFF : SW2_OFF);
#pragma unroll
        for (int i = 0; i < 2; i++)
#pragma unroll
            for (int j = 0; j < 8; j++)
#pragma unroll
                for (int q = 0; q < 4; q++) c[i][j][q] = 0.f;

#pragma unroll 1
        for (int t = 0; t < 3; t++) {
            const int akoff = (t == 2) ? 256 : 0;
            const int bkoff = (t == 1) ? 256 : 0;
#pragma unroll
            for (int ks = 0; ks < 8; ks++) {
                const int kb = ks * 32;
                uint32_t fa[2][4], fb[8][2];
#pragma unroll
                for (int i = 0; i < 2; i++)
                    ldsm4(fa[i][0], fa[i][1], fa[i][2], fa[i][3],
                          abase[i] + (uint32_t)((kb + akoff + akadd) ^ lxor));
#pragma unroll
                for (int jj = 0; jj < 4; jj++) {
                    uint32_t r0, r1, r2, r3;
                    ldsm4(r0, r1, r2, r3,
                          woff + bbase[jj] + (uint32_t)((kb + bkoff + bkadd) ^ lxor));
                    fb[2 * jj][0] = r0; fb[2 * jj][1] = r1;
                    fb[2 * jj + 1][0] = r2; fb[2 * jj + 1][1] = r3;
                }
#pragma unroll
                for (int i = 0; i < 2; i++)
#pragma unroll
                    for (int j = 0; j < 8; j++)
                        mma16816(c[i][j], fa[i], fb[j]);
            }
        }

        if (g == 0) {
            __syncthreads();
#pragma unroll
            for (int j = 0; j < 8; j++) {
                int n = ncol0 + 8 * j + 2 * (lane & 3);
                float bn0 = __ldg(&b1[n]), bn1 = __ldg(&b1[n + 1]);
#pragma unroll
                for (int i = 0; i < 2; i++) {
                    int r0 = m0w + 16 * i + (lane >> 2);
                    float h0 = fmaxf(c[i][j][0] + bn0, 0.f);
                    float h1 = fmaxf(c[i][j][1] + bn1, 0.f);
                    float h2 = fmaxf(c[i][j][2] + bn0, 0.f);
                    float h3 = fmaxf(c[i][j][3] + bn1, 0.f);
                    float t0 = __bfloat162float(__float2bfloat16(h0));
                    float t1 = __bfloat162float(__float2bfloat16(h1));
                    float t2 = __bfloat162float(__float2bfloat16(h2));
                    float t3 = __bfloat162float(__float2bfloat16(h3));
                    *(uint32_t*)(smem + sws(r0, 2 * n))           = pack_bf16(h0, h1);
                    *(uint32_t*)(smem + sws(r0, 256 + 2 * n))     = pack_bf16(h0 - t0, h1 - t1);
                    *(uint32_t*)(smem + sws(r0 + 8, 2 * n))       = pack_bf16(h2, h3);
                    *(uint32_t*)(smem + sws(r0 + 8, 256 + 2 * n)) = pack_bf16(h2 - t2, h3 - t3);
                }
            }
            __syncthreads();
        }
    }

    // ---- epilogue 2: bias (+relu), write fp16 g_xs16[layer] ----
    {
        const int relu_out = (layer < 2);
        __half* outp = g_xs16 + (size_t)layer * NN * DD;
#pragma unroll
        for (int j = 0; j < 8; j++) {
            int n = ncol0 + 8 * j + 2 * (lane & 3);
            float bn0 = __ldg(&b2[n]), bn1 = __ldg(&b2[n + 1]);
#pragma unroll
            for (int i = 0; i < 2; i++) {
                int r0 = base + m0w + 16 * i + (lane >> 2);
                float o0 = c[i][j][0] + bn0, o1 = c[i][j][1] + bn1;
                float o2 = c[i][j][2] + bn0, o3 = c[i][j][3] + bn1;
                if (relu_out) {
                    o0 = fmaxf(o0, 0.f); o1 = fmaxf(o1, 0.f);
                    o2 = fmaxf(o2, 0.f); o3 = fmaxf(o3, 0.f);
                }
                if (r0 < NN)
                    *(__half2*)(outp + (size_t)r0 * DD + n) = __floats2half2_rn(o0, o1);
                if (r0 + 8 < NN)
                    *(__half2*)(outp + (size_t)(r0 + 8) * DD + n) = __floats2half2_rn(o2, o3);
            }
        }
    }
}

// ---------------- readout: fp16 activations ----------------
__global__ void k_readout(const float* __restrict__ Wm, const float* __restrict__ bm,
                          float* __restrict__ out) {
    int gw = (blockIdx.x * blockDim.x + threadIdx.x) >> 5;
    if (gw >= NN) return;
    int lane = threadIdx.x & 31;
    float acc = 0.f;
#pragma unroll
    for (int l = 0; l < 3; l++) {
        const uint2* xs2 = (const uint2*)(g_xs16 + (size_t)l * NN * DD);
        float4 v = h4tof4(xs2[(size_t)gw * 32 + lane]);
        float4 w = __ldg(&((const float4*)(Wm + l * 128))[lane]);
        acc += v.x * w.x + v.y * w.y + v.z * w.z + v.w * w.w;
    }
#pragma unroll
    for (int o = 16; o; o >>= 1) acc += __shfl_xor_sync(0xffffffffu, acc, o);
    if (lane == 0) {
        float z = acc + __ldg(bm);
        out[gw] = 1.0f / (1.0f + expf(-z));
    }
}

// ---------------- launch ----------------
extern "C" void kernel_launch(void* const* d_in, const int* in_sizes, int n_in,
                              void* d_out, int out_size) {
    const float* x  = (const float*)d_in[0];
    const int*   ei = (const int*)d_in[1];
    const float* W1[3] = {(const float*)d_in[3],  (const float*)d_in[7],  (const float*)d_in[11]};
    const float* b1[3] = {(const float*)d_in[4],  (const float*)d_in[8],  (const float*)d_in[12]};
    const float* W2[3] = {(const float*)d_in[5],  (const float*)d_in[9],  (const float*)d_in[13]};
    const float* b2[3] = {(const float*)d_in[6],  (const float*)d_in[10], (const float*)d_in[14]};
    const float* Wm = (const float*)d_in[15];
    const float* bm = (const float*)d_in[16];
    float* out = (float*)d_out;

    cudaFuncSetAttribute(k_mlp, cudaFuncAttributeMaxDynamicSharedMemorySize, SMEM_MLP);

    // CSR build + prep (deterministic every launch)
    k_detect<<<1, 32>>>(ei);
    k_zero<<<(NN + 255) / 256, 256>>>();
    k_hist<<<(NE + 255) / 256, 256>>>(ei);
    k_scan1<<<NSB, SCAN_BLK>>>();
    k_scan2<<<1, 128>>>();
    k_scan3<<<NSB, SCAN_BLK>>>();
    k_scatter<<<(NE + 255) / 256, 256>>>(ei);
    k_wprep<<<(6 * 128 * 128 + 255) / 256, 256>>>(W1[0], W2[0], W1[1], W2[1], W1[2], W2[2]);
    k_xprep<<<(NN * DD / 4 + 255) / 256, 256>>>(x);

    const int AGG_BLOCKS = (NN * 32 + 255) / 256;   // 12500
    const int MLP_BLOCKS = (NN + 127) / 128;        // 782

    for (int l = 0; l < 3; l++) {
        k_agg<<<AGG_BLOCKS, 256>>>(l);
        k_mlp<<<MLP_BLOCKS, 256, SMEM_MLP>>>(b1[l], b2[l], l);
    }
    k_readout<<<AGG_BLOCKS, 256>>>(Wm, bm, out);
}

// round 11
// speedup vs baseline: 2.1847x; 1.0180x over previous
#include <cuda_runtime.h>
#include <cuda_bf16.h>
#include <cuda_fp16.h>
#include <stdint.h>
#include <math.h>

#define NN 100000
#define NE 1600000
#define DD 128
#define SCAN_BLK 1024
#define NSB ((NN + SCAN_BLK - 1) / SCAN_BLK)   // 98 scan blocks

// ---------------- scratch (device globals; no allocation) ----------------
__device__ alignas(16) float  g_agg[(size_t)NN * DD];         // 51.2 MB (fp32 MLP input)
__device__ alignas(16) __half g_x16[(size_t)NN * DD];         // 25.6 MB (fp16 input copy)
__device__ alignas(16) __half g_xs16[(size_t)3 * NN * DD];    // 76.8 MB (fp16 layer outputs)
__device__ alignas(16) __nv_bfloat16 g_wb[6 * 128 * 256];     // split weights [mat][n][k: hi|lo]
__device__ alignas(16) int   g_deg[NN];
__device__ alignas(16) int   g_cur[NN];
__device__ alignas(16) int   g_srcs[NE];
__device__ alignas(16) int   g_off[NN + 1];
__device__ alignas(16) int   g_bsum[NSB];
__device__ alignas(16) int   g_bpre[NSB];
__device__ int g_is64;

__device__ __forceinline__ uint32_t smem_u32(const void* p) {
    uint32_t a;
    asm("{ .reg .u64 t; cvta.to.shared.u64 t, %1; cvt.u32.u64 %0, t; }" : "=r"(a) : "l"(p));
    return a;
}
__device__ __forceinline__ uint32_t pack_bf16(float a, float b) {
    __nv_bfloat16 ha = __float2bfloat16(a), hb = __float2bfloat16(b);
    return (uint32_t)__bfloat16_as_ushort(ha) | ((uint32_t)__bfloat16_as_ushort(hb) << 16);
}
__device__ __forceinline__ void ldsm4(uint32_t& r0, uint32_t& r1, uint32_t& r2, uint32_t& r3, uint32_t addr) {
    asm volatile("ldmatrix.sync.aligned.m8n8.x4.shared.b16 {%0,%1,%2,%3}, [%4];"
                 : "=r"(r0), "=r"(r1), "=r"(r2), "=r"(r3) : "r"(addr));
}
__device__ __forceinline__ void mma16816(float* c, const uint32_t* a, const uint32_t* b) {
    asm volatile("mma.sync.aligned.m16n8k16.row.col.f32.bf16.bf16.f32 "
                 "{%0,%1,%2,%3}, {%4,%5,%6,%7}, {%8,%9}, {%0,%1,%2,%3};"
                 : "+f"(c[0]), "+f"(c[1]), "+f"(c[2]), "+f"(c[3])
                 : "r"(a[0]), "r"(a[1]), "r"(a[2]), "r"(a[3]), "r"(b[0]), "r"(b[1]));
}
// swizzled smem byte offset within a 512B bf16 row (k: hi bytes 0-255, lo 256-511)
__device__ __forceinline__ uint32_t sws(int row, int kb) {
    return (uint32_t)(row * 512 + (kb ^ ((row & 7) << 4)));
}
// unpack 4 packed halves (uint2) -> float4
__device__ __forceinline__ float4 h4tof4(uint2 u) {
    __half2 h0 = *(__half2*)&u.x, h1 = *(__half2*)&u.y;
    float2 f0 = __half22float2(h0), f1 = __half22float2(h1);
    return make_float4(f0.x, f0.y, f1.x, f1.y);
}

// ---------------- dtype probe ----------------
__global__ void k_detect(const int* __restrict__ ei32) {
    int lane = threadIdx.x;
    int nz = 0;
#pragma unroll
    for (int i = 0; i < 2; i++) {
        int w = ei32[2 * (lane + 32 * i) + 1];
        nz |= (w != 0);
    }
    unsigned any = __ballot_sync(0xffffffffu, nz);
    if (lane == 0) g_is64 = (any == 0u) ? 1 : 0;
}

// ---------------- input fp32 -> fp16 ----------------
__global__ void k_xprep(const float* __restrict__ x) {
    int i = blockIdx.x * blockDim.x + threadIdx.x;   // over NN*DD/4
    if (i < NN * DD / 4) {
        float4 v = ((const float4*)x)[i];
        __half2 a = __floats2half2_rn(v.x, v.y);
        __half2 b = __floats2half2_rn(v.z, v.w);
        ((__half2*)g_x16)[2 * i]     = a;
        ((__half2*)g_x16)[2 * i + 1] = b;
    }
}

// ---------------- CSR build ----------------
__global__ void k_zero() {
    int i = blockIdx.x * blockDim.x + threadIdx.x;
    if (i < NN) g_deg[i] = 0;
}
__global__ void k_hist(const int* __restrict__ ei32) {
    int e = blockIdx.x * blockDim.x + threadIdx.x;
    if (e < NE) {
        int is64 = g_is64;
        unsigned d = is64 ? (unsigned)ei32[2 * (NE + e)] : (unsigned)ei32[NE + e];
        if (d < NN) atomicAdd(&g_deg[d], 1);
    }
}
__global__ void k_scan1() {
    __shared__ int ws[32];
    int i = blockIdx.x * SCAN_BLK + threadIdx.x;
    int v = (i < NN) ? g_deg[i] : 0;
    int s = v;
#pragma unroll
    for (int o = 16; o; o >>= 1) s += __shfl_xor_sync(0xffffffffu, s, o);
    if ((threadIdx.x & 31) == 0) ws[threadIdx.x >> 5] = s;
    __syncthreads();
    if (threadIdx.x < 32) {
        int t = ws[threadIdx.x];
#pragma unroll
        for (int o = 16; o; o >>= 1) t += __shfl_xor_sync(0xffffffffu, t, o);
        if (threadIdx.x == 0) g_bsum[blockIdx.x] = t;
    }
}
__global__ void k_scan2() {
    __shared__ int warp_incl[4];
    int t = threadIdx.x;
    int v = (t < NSB) ? g_bsum[t] : 0;
    int incl = v;
#pragma unroll
    for (int o = 1; o < 32; o <<= 1) {
        int u = __shfl_up_sync(0xffffffffu, incl, o);
        if ((t & 31) >= o) incl += u;
    }
    if ((t & 31) == 31) warp_incl[t >> 5] = incl;
    __syncthreads();
    int base = 0;
#pragma unroll
    for (int w = 0; w < 4; w++)
        if ((t >> 5) > w) base += warp_incl[w];
    incl += base;
    if (t < NSB) g_bpre[t] = incl - v;
    if (t == NSB - 1) g_off[NN] = incl;
}
// block-local exclusive scan via warp shuffles (2 syncs instead of 20)
__global__ void k_scan3() {
    __shared__ int wsum[32];
    int t = threadIdx.x;
    int i = blockIdx.x * SCAN_BLK + t;
    int v = (i < NN) ? g_deg[i] : 0;
    int lane = t & 31, wrp = t >> 5;
    int incl = v;
#pragma unroll
    for (int o = 1; o < 32; o <<= 1) {
        int u = __shfl_up_sync(0xffffffffu, incl, o);
        if (lane >= o) incl += u;
    }
    if (lane == 31) wsum[wrp] = incl;
    __syncthreads();
    if (wrp == 0) {
        int w = wsum[lane];
        int wincl = w;
#pragma unroll
        for (int o = 1; o < 32; o <<= 1) {
            int u = __shfl_up_sync(0xffffffffu, wincl, o);
            if (lane >= o) wincl += u;
        }
        wsum[lane] = wincl - w;   // exclusive warp base
    }
    __syncthreads();
    if (i < NN) {
        int off = g_bpre[blockIdx.x] + wsum[wrp] + incl - v;
        g_off[i] = off;
        g_cur[i] = off;
    }
}
__global__ void k_scatter(const int* __restrict__ ei32) {
    int e = blockIdx.x * blockDim.x + threadIdx.x;
    if (e < NE) {
        int is64 = g_is64;
        unsigned d    = is64 ? (unsigned)ei32[2 * (NE + e)] : (unsigned)ei32[NE + e];
        unsigned srcv = is64 ? (unsigned)ei32[2 * e]        : (unsigned)ei32[e];
        if (d < NN && srcv < NN) {
            int pos = atomicAdd(&g_cur[d], 1);
            g_srcs[pos] = (int)srcv;
        }
    }
}

// ---------------- weight prep: W[k][n] fp32 -> bf16 hi/lo transposed [n][hi(k)|lo(k)] ----------------
__global__ void k_wprep(const float* __restrict__ w0, const float* __restrict__ w1,
                        const float* __restrict__ w2, const float* __restrict__ w3,
                        const float* __restrict__ w4, const float* __restrict__ w5) {
    int idx = blockIdx.x * blockDim.x + threadIdx.x;   // 6*128*128
    if (idx >= 6 * 128 * 128) return;
    int mat = idx >> 14;
    int k = (idx >> 7) & 127;
    int n = idx & 127;
    const float* W = (mat == 0) ? w0 : (mat == 1) ? w1 : (mat == 2) ? w2
                   : (mat == 3) ? w3 : (mat == 4) ? w4 : w5;
    float v = W[k * 128 + n];
    __nv_bfloat16 hi = __float2bfloat16(v);
    __nv_bfloat16 lo = __float2bfloat16(v - __bfloat162float(hi));
    __nv_bfloat16* dst = g_wb + (size_t)mat * 128 * 256 + (size_t)n * 256;
    dst[k] = hi;
    dst[128 + k] = lo;
}

// ---------------- aggregation: fp16 gather (256B rows), fp32 accumulate, unroll-4 ----------------
__global__ void k_agg(int layer) {
    int gw = (blockIdx.x * blockDim.x + threadIdx.x) >> 5;
    if (gw >= NN) return;
    int lane = threadIdx.x & 31;
    const __half* xin = (layer == 0) ? g_x16 : (g_xs16 + (size_t)(layer - 1) * NN * DD);
    const uint2* x2 = (const uint2*)xin;   // 4 halves per lane, 32 lanes = 256B row

    float4 acc = h4tof4(x2[(size_t)gw * 32 + lane]);
    int j = g_off[gw];
    int end = g_off[gw + 1];
    for (; j + 3 < end; j += 4) {
        int s0 = g_srcs[j], s1 = g_srcs[j + 1], s2 = g_srcs[j + 2], s3 = g_srcs[j + 3];
        uint2 ua = __ldg(&x2[(size_t)s0 * 32 + lane]);
        uint2 ub = __ldg(&x2[(size_t)s1 * 32 + lane]);
        uint2 uc = __ldg(&x2[(size_t)s2 * 32 + lane]);
        uint2 ud = __ldg(&x2[(size_t)s3 * 32 + lane]);
        float4 a = h4tof4(ua), b = h4tof4(ub), c = h4tof4(uc), d = h4tof4(ud);
        acc.x += (a.x + b.x) + (c.x + d.x);
        acc.y += (a.y + b.y) + (c.y + d.y);
        acc.z += (a.z + b.z) + (c.z + d.z);
        acc.w += (a.w + b.w) + (c.w + d.w);
    }
    for (; j < end; j++) {
        float4 a = h4tof4(__ldg(&x2[(size_t)g_srcs[j] * 32 + lane]));
        acc.x += a.x; acc.y += a.y; acc.z += a.z; acc.w += a.w;
    }
    ((float4*)g_agg)[(size_t)gw * 32 + lane] = acc;
}

// ---------------- mma.sync bf16 MLP: 128x128 tile per CTA ----------------
// smem: A @0 (128 rows x 512B = 64KB), W1 @65536 (64KB), W2 @131072 (64KB)
#define SW1_OFF 65536u
#define SW2_OFF 131072u
#define SMEM_MLP 196608

__global__ __launch_bounds__(256)
void k_mlp(const float* __restrict__ b1, const float* __restrict__ b2, int layer)
{
    extern __shared__ char smem[];
    const uint32_t sa = smem_u32(smem);
    const int tid = threadIdx.x, wid = tid >> 5, lane = tid & 31;
    const int base = blockIdx.x * 128;
    const int wm = wid & 3, wn = wid >> 2;
    const int m0w = wm * 32;            // warp's 32 rows
    const int ncol0 = wn * 64;          // warp's 64 cols
    const int lr = lane & 7, grp = lane >> 3;
    const __nv_bfloat16* wb1 = g_wb + (size_t)(layer * 2)     * 128 * 256;
    const __nv_bfloat16* wb2 = g_wb + (size_t)(layer * 2 + 1) * 128 * 256;

    // ---- build A (split hi/lo) from fp32 g_agg ----
    {
        const float4* in4 = (const float4*)g_agg;
        int kb = lane * 8;
#pragma unroll 4
        for (int it = 0; it < 16; it++) {
            int m = wid + it * 8;
            int node = base + m;
            float4 v = make_float4(0.f, 0.f, 0.f, 0.f);
            if (node < NN) v = in4[(size_t)node * 32 + lane];
            float hx = __bfloat162float(__float2bfloat16(v.x));
            float hy = __bfloat162float(__float2bfloat16(v.y));
            float hz = __bfloat162float(__float2bfloat16(v.z));
            float hw = __bfloat162float(__float2bfloat16(v.w));
            uint2 hi = make_uint2(pack_bf16(v.x, v.y), pack_bf16(v.z, v.w));
            uint2 lo = make_uint2(pack_bf16(v.x - hx, v.y - hy), pack_bf16(v.z - hz, v.w - hw));
            *(uint2*)(smem + sws(m, kb))       = hi;
            *(uint2*)(smem + sws(m, 256 + kb)) = lo;
        }
    }
    // ---- load W1/W2 into swizzled smem ----
    {
        int kb = lane * 16;
#pragma unroll 4
        for (int it = 0; it < 16; it++) {
            int n = wid + it * 8;
            uint4 r1 = ((const uint4*)(wb1 + (size_t)n * 256))[lane];
            uint4 r2 = ((const uint4*)(wb2 + (size_t)n * 256))[lane];
            uint32_t o = sws(n, kb);
            *(uint4*)(smem + SW1_OFF + o) = r1;
            *(uint4*)(smem + SW2_OFF + o) = r2;
        }
    }
    __syncthreads();

    const int arow = lr + ((grp & 1) << 3);
    const int akadd = (grp & 2) ? 16 : 0;
    const int brow = lr + ((grp & 2) << 2);
    const int bkadd = (grp & 1) ? 16 : 0;
    const uint32_t lxor = (uint32_t)(lr << 4);
    uint32_t abase[2], bbase[4];
#pragma unroll
    for (int i = 0; i < 2; i++) abase[i] = sa + (uint32_t)((m0w + 16 * i + arow) * 512);
#pragma unroll
    for (int j = 0; j < 4; j++) bbase[j] = (uint32_t)((ncol0 + 16 * j + brow) * 512);

    float c[2][8][4];

#pragma unroll 1
    for (int g = 0; g < 2; g++) {
        const uint32_t woff = sa + (g == 0 ? SW1_OFF : SW2_OFF);
#pragma unroll
        for (int i = 0; i < 2; i++)
#pragma unroll
            for (int j = 0; j < 8; j++)
#pragma unroll
                for (int q = 0; q < 4; q++) c[i][j][q] = 0.f;

#pragma unroll 1
        for (int t = 0; t < 3; t++) {
            const int akoff = (t == 2) ? 256 : 0;
            const int bkoff = (t == 1) ? 256 : 0;
#pragma unroll
            for (int ks = 0; ks < 8; ks++) {
                const int kb = ks * 32;
                uint32_t fa[2][4], fb[8][2];
#pragma unroll
                for (int i = 0; i < 2; i++)
                    ldsm4(fa[i][0], fa[i][1], fa[i][2], fa[i][3],
                          abase[i] + (uint32_t)((kb + akoff + akadd) ^ lxor));
#pragma unroll
                for (int jj = 0; jj < 4; jj++) {
                    uint32_t r0, r1, r2, r3;
                    ldsm4(r0, r1, r2, r3,
                          woff + bbase[jj] + (uint32_t)((kb + bkoff + bkadd) ^ lxor));
                    fb[2 * jj][0] = r0; fb[2 * jj][1] = r1;
                    fb[2 * jj + 1][0] = r2; fb[2 * jj + 1][1] = r3;
                }
#pragma unroll
                for (int i = 0; i < 2; i++)
#pragma unroll
                    for (int j = 0; j < 8; j++)
                        mma16816(c[i][j], fa[i], fb[j]);
            }
        }

        if (g == 0) {
            __syncthreads();
#pragma unroll
            for (int j = 0; j < 8; j++) {
                int n = ncol0 + 8 * j + 2 * (lane & 3);
                float bn0 = __ldg(&b1[n]), bn1 = __ldg(&b1[n + 1]);
#pragma unroll
                for (int i = 0; i < 2; i++) {
                    int r0 = m0w + 16 * i + (lane >> 2);
                    float h0 = fmaxf(c[i][j][0] + bn0, 0.f);
                    float h1 = fmaxf(c[i][j][1] + bn1, 0.f);
                    float h2 = fmaxf(c[i][j][2] + bn0, 0.f);
                    float h3 = fmaxf(c[i][j][3] + bn1, 0.f);
                    float t0 = __bfloat162float(__float2bfloat16(h0));
                    float t1 = __bfloat162float(__float2bfloat16(h1));
                    float t2 = __bfloat162float(__float2bfloat16(h2));
                    float t3 = __bfloat162float(__float2bfloat16(h3));
                    *(uint32_t*)(smem + sws(r0, 2 * n))           = pack_bf16(h0, h1);
                    *(uint32_t*)(smem + sws(r0, 256 + 2 * n))     = pack_bf16(h0 - t0, h1 - t1);
                    *(uint32_t*)(smem + sws(r0 + 8, 2 * n))       = pack_bf16(h2, h3);
                    *(uint32_t*)(smem + sws(r0 + 8, 256 + 2 * n)) = pack_bf16(h2 - t2, h3 - t3);
                }
            }
            __syncthreads();
        }
    }

    // ---- epilogue 2: bias (+relu), write fp16 g_xs16[layer] ----
    {
        const int relu_out = (layer < 2);
        __half* outp = g_xs16 + (size_t)layer * NN * DD;
#pragma unroll
        for (int j = 0; j < 8; j++) {
            int n = ncol0 + 8 * j + 2 * (lane & 3);
            float bn0 = __ldg(&b2[n]), bn1 = __ldg(&b2[n + 1]);
#pragma unroll
            for (int i = 0; i < 2; i++) {
                int r0 = base + m0w + 16 * i + (lane >> 2);
                float o0 = c[i][j][0] + bn0, o1 = c[i][j][1] + bn1;
                float o2 = c[i][j][2] + bn0, o3 = c[i][j][3] + bn1;
                if (relu_out) {
                    o0 = fmaxf(o0, 0.f); o1 = fmaxf(o1, 0.f);
                    o2 = fmaxf(o2, 0.f); o3 = fmaxf(o3, 0.f);
                }
                if (r0 < NN)
                    *(__half2*)(outp + (size_t)r0 * DD + n) = __floats2half2_rn(o0, o1);
                if (r0 + 8 < NN)
                    *(__half2*)(outp + (size_t)(r0 + 8) * DD + n) = __floats2half2_rn(o2, o3);
            }
        }
    }
}

// ---------------- readout: fp16 activations ----------------
__global__ void k_readout(const float* __restrict__ Wm, const float* __restrict__ bm,
                          float* __restrict__ out) {
    int gw = (blockIdx.x * blockDim.x + threadIdx.x) >> 5;
    if (gw >= NN) return;
    int lane = threadIdx.x & 31;
    float acc = 0.f;
#pragma unroll
    for (int l = 0; l < 3; l++) {
        const uint2* xs2 = (const uint2*)(g_xs16 + (size_t)l * NN * DD);
        float4 v = h4tof4(xs2[(size_t)gw * 32 + lane]);
        float4 w = __ldg(&((const float4*)(Wm + l * 128))[lane]);
        acc += v.x * w.x + v.y * w.y + v.z * w.z + v.w * w.w;
    }
#pragma unroll
    for (int o = 16; o; o >>= 1) acc += __shfl_xor_sync(0xffffffffu, acc, o);
    if (lane == 0) {
        float z = acc + __ldg(bm);
        out[gw] = 1.0f / (1.0f + expf(-z));
    }
}

// ---------------- launch ----------------
extern "C" void kernel_launch(void* const* d_in, const int* in_sizes, int n_in,
                              void* d_out, int out_size) {
    const float* x  = (const float*)d_in[0];
    const int*   ei = (const int*)d_in[1];
    const float* W1[3] = {(const float*)d_in[3],  (const float*)d_in[7],  (const float*)d_in[11]};
    const float* b1[3] = {(const float*)d_in[4],  (const float*)d_in[8],  (const float*)d_in[12]};
    const float* W2[3] = {(const float*)d_in[5],  (const float*)d_in[9],  (const float*)d_in[13]};
    const float* b2[3] = {(const float*)d_in[6],  (const float*)d_in[10], (const float*)d_in[14]};
    const float* Wm = (const float*)d_in[15];
    const float* bm = (const float*)d_in[16];
    float* out = (float*)d_out;

    cudaFuncSetAttribute(k_mlp, cudaFuncAttributeMaxDynamicSharedMemorySize, SMEM_MLP);

    // CSR build + prep (deterministic every launch)
    k_detect<<<1, 32>>>(ei);
    k_zero<<<(NN + 255) / 256, 256>>>();
    k_hist<<<(NE + 255) / 256, 256>>>(ei);
    k_scan1<<<NSB, SCAN_BLK>>>();
    k_scan2<<<1, 128>>>();
    k_scan3<<<NSB, SCAN_BLK>>>();
    k_scatter<<<(NE + 255) / 256, 256>>>(ei);
    k_wprep<<<(6 * 128 * 128 + 255) / 256, 256>>>(W1[0], W2[0], W1[1], W2[1], W1[2], W2[2]);
    k_xprep<<<(NN * DD / 4 + 255) / 256, 256>>>(x);

    const int AGG_BLOCKS = (NN * 32 + 255) / 256;   // 12500
    const int MLP_BLOCKS = (NN + 127) / 128;        // 782

    for (int l = 0; l < 3; l++) {
        k_agg<<<AGG_BLOCKS, 256>>>(l);
        k_mlp<<<MLP_BLOCKS, 256, SMEM_MLP>>>(b1[l], b2[l], l);
    }
    k_readout<<<AGG_BLOCKS, 256>>>(Wm, bm, out);
}